// round 13
// baseline (speedup 1.0000x reference)
#include <cuda_runtime.h>
#include <cuda_fp16.h>
#include <cstdint>

#define BB 4
#define CH 1024
#define HH 50
#define WW 50
#define KK 512
#define NPIX (HH*WW)              // 2500
#define GPTS 8

// NHWC-transposed features in fp16: [B][H][W][C]  (20.5 MB scratch)
__device__ __align__(16) __half FT[BB * HH * WW * CH];

__device__ __forceinline__ uint32_t smem_u32(const void* p) {
    uint32_t a;
    asm("{ .reg .u64 t; cvta.to.shared.u64 t, %1; cvt.u32.u64 %0, t; }"
        : "=r"(a) : "l"(p));
    return a;
}
#define CP_ASYNC16(s, g) \
    asm volatile("cp.async.ca.shared.global [%0], [%1], 16;" :: "r"(s), "l"(g))
template<int N> __device__ __forceinline__ void cp_wait() {
    asm volatile("cp.async.wait_group %0;" :: "n"(N));
}
__device__ __forceinline__ void cp_commit() {
    asm volatile("cp.async.commit_group;");
}

// ---------------------------------------------------------------------------
// Kernel 1: NCHW fp32 -> NHWC fp16 transpose-convert (measured ~12us)
// ---------------------------------------------------------------------------
__global__ __launch_bounds__(256)
void transpose_kernel(const float* __restrict__ f) {
    __shared__ __align__(16) float tile[32][133];
    const int b  = blockIdx.z;
    const int p0 = blockIdx.x * 128;
    const int c0 = blockIdx.y * 32;
    const int t  = threadIdx.x;

    const float* fb = f + (size_t)b * CH * NPIX + (size_t)c0 * NPIX;
    #pragma unroll
    for (int j = 0; j < 4; j++) {
        int idx = t + j * 256;
        int c = idx >> 5;
        int q = idx & 31;
        int p = p0 + 4 * q;
        float4 v = make_float4(0.f, 0.f, 0.f, 0.f);
        if (p < NPIX) v = *(const float4*)(fb + (size_t)c * NPIX + p);
        tile[c][4 * q + 0] = v.x;
        tile[c][4 * q + 1] = v.y;
        tile[c][4 * q + 2] = v.z;
        tile[c][4 * q + 3] = v.w;
    }
    __syncthreads();

    __half* ob = FT + (size_t)b * NPIX * CH + c0;
    #pragma unroll
    for (int j = 0; j < 2; j++) {
        int idx = t + j * 256;
        int p = idx >> 2;
        int g = idx & 3;
        if (p0 + p < NPIX) {
            __half2 h0 = __floats2half2_rn(tile[8*g + 0][p], tile[8*g + 1][p]);
            __half2 h1 = __floats2half2_rn(tile[8*g + 2][p], tile[8*g + 3][p]);
            __half2 h2 = __floats2half2_rn(tile[8*g + 4][p], tile[8*g + 5][p]);
            __half2 h3 = __floats2half2_rn(tile[8*g + 6][p], tile[8*g + 7][p]);
            uint4 v;
            v.x = *(const unsigned int*)&h0;
            v.y = *(const unsigned int*)&h1;
            v.z = *(const unsigned int*)&h2;
            v.w = *(const unsigned int*)&h3;
            *(uint4*)(ob + (size_t)(p0 + p) * CH + 8 * g) = v;
        }
    }
}

// ---------------------------------------------------------------------------
// Kernel 2: fused RoIAlign + 2x2 avg pool (R10 frame, scalar math).
// Grid (K,2): 512 ch/CTA, 256 threads, 2 ch/thread, 8-row sweep.
// cp.async taps triple-buffered (lookahead 2), ONE barrier per row.
// 49xfloat2 accumulator; 2-chunk (256ch) staged float4 drain.
// ---------------------------------------------------------------------------
#define TB_BYTES 32768            // one tap buffer: 32 segs x 1KB

extern __shared__ __align__(16) unsigned char dynsmem[];   // 3*TB_BYTES

__global__ __launch_bounds__(256, 2)
void roi_pool_kernel(const float* __restrict__ rois, float* __restrict__ out) {
    const int k     = blockIdx.x;
    const int chunk = blockIdx.y;          // channel half
    const int tid   = threadIdx.x;

    __shared__ __align__(16) float s_w[GPTS][GPTS][4];
    __shared__ float s_wx[GPTS], s_wy[GPTS], s_vx[GPTS], s_vy[GPTS];
    __shared__ int   s_x0[GPTS], s_y0[GPTS];
    __shared__ int   s_b;

    if (tid < GPTS) {
        float x1 = __ldg(&rois[k * 5 + 1]) * 0.0625f;
        float y1 = __ldg(&rois[k * 5 + 2]) * 0.0625f;
        float x2 = __ldg(&rois[k * 5 + 3]) * 0.0625f;
        float y2 = __ldg(&rois[k * 5 + 4]) * 0.0625f;
        float bh = fmaxf(y2 - y1, 0.0f) * (1.0f / 7.0f);
        float bw = fmaxf(x2 - x1, 0.0f) * (1.0f / 7.0f);
        float xv = x1 + (float)tid * bw;
        float yv = y1 + (float)tid * bh;
        s_vx[tid] = (xv >= 0.0f && xv < (float)WW) ? 1.0f : 0.0f;
        s_vy[tid] = (yv >= 0.0f && yv < (float)HH) ? 1.0f : 0.0f;
        int x0 = (int)floorf(xv);  x0 = min(max(x0, 0), WW - 2);
        int y0 = (int)floorf(yv);  y0 = min(max(y0, 0), HH - 2);
        s_x0[tid] = x0;  s_y0[tid] = y0;
        s_wx[tid] = xv - (float)x0;
        s_wy[tid] = yv - (float)y0;
        if (tid == 0) s_b = (int)__ldg(&rois[k * 5 + 0]);
    }
    __syncthreads();

    // gather role: t4 = tap, col = 16B chunk within 1KB segment
    const int t4  = tid >> 6;
    const int dy  = t4 >> 1, dx = t4 & 1;
    const int col = tid & 63;
    const __half* bbase = FT + (size_t)s_b * (NPIX * CH) + chunk * 512
                             + (size_t)dx * CH + col * 8;
    int xoff[GPTS];
    #pragma unroll
    for (int gx = 0; gx < GPTS; gx++) xoff[gx] = s_x0[gx] * CH;

    const uint32_t tb0 = smem_u32(dynsmem);
    const uint32_t smy = tb0 + (t4 * 1024 + col * 16);

    #define GATHER(gy, bi)                                                  \
        do {                                                                \
            const __half* rb = bbase + (size_t)(s_y0[gy] + dy) * (WW * CH); \
            uint32_t sb = smy + (bi) * TB_BYTES;                            \
            _Pragma("unroll")                                               \
            for (int j = 0; j < 8; j++)                                     \
                CP_ASYNC16(sb + j * 4096, rb + xoff[j]);                    \
            cp_commit();                                                    \
        } while (0)

    // issue first two row-gathers BEFORE the weight-table work
    GATHER(0, 0);
    GATHER(1, 1);

    // folded bilinear weights (overlap with in-flight gathers)
    if (tid < 64) {
        int gy = tid >> 3, gx = tid & 7;
        float wy = s_wy[gy], wx = s_wx[gx];
        float sc = 0.25f * s_vy[gy] * s_vx[gx];
        s_w[gy][gx][0] = (1.0f - wy) * (1.0f - wx) * sc;
        s_w[gy][gx][1] = (1.0f - wy) * wx * sc;
        s_w[gy][gx][2] = wy * (1.0f - wx) * sc;
        s_w[gy][gx][3] = wy * wx * sc;
    }

    float2 acc[49];
    #pragma unroll
    for (int i = 0; i < 49; i++) { acc[i].x = 0.0f; acc[i].y = 0.0f; }

    #pragma unroll
    for (int g = 0; g < GPTS; g++) {
        if (g < GPTS - 1) cp_wait<1>(); else cp_wait<0>();   // row g landed
        __syncthreads();   // row-g visible to all; buf[(g+2)%3] readers done
        if (g + 2 < GPTS) GATHER(g + 2, (g + 2) % 3);

        const unsigned char* buf = dynsmem + (g % 3) * TB_BYTES;
        float2 rh[7];
        float2 cprev = make_float2(0.f, 0.f);
        #pragma unroll
        for (int gx = 0; gx < GPTS; gx++) {
            const float4 w = *(const float4*)&s_w[g][gx][0];
            const unsigned char* sp = buf + (gx * 4) * 1024 + tid * 4;
            float2 f00 = __half22float2(*(const __half2*)(sp));
            float2 f01 = __half22float2(*(const __half2*)(sp + 1024));
            float2 f10 = __half22float2(*(const __half2*)(sp + 2048));
            float2 f11 = __half22float2(*(const __half2*)(sp + 3072));

            float2 cur;
            cur.x = f00.x*w.x + f01.x*w.y + f10.x*w.z + f11.x*w.w;
            cur.y = f00.y*w.x + f01.y*w.y + f10.y*w.z + f11.y*w.w;

            if (gx > 0) {
                rh[gx-1].x = cprev.x + cur.x;
                rh[gx-1].y = cprev.y + cur.y;
            }
            cprev = cur;
        }
        // rowsums feed pooled rows g-1 and g
        #pragma unroll
        for (int px = 0; px < 7; px++) {
            if (g >= 1) { acc[(g-1)*7 + px].x += rh[px].x; acc[(g-1)*7 + px].y += rh[px].y; }
            if (g <  7) { acc[ g   *7 + px].x += rh[px].x; acc[ g   *7 + px].y += rh[px].y; }
        }
    }
    #undef GATHER

    // ---- 2-chunk staged drain (256 ch per pass; aliases gather bufs) ----
    float* sbuf = (float*)dynsmem;         // 256*49 floats = 50176 B < 96 KB
    float* outk = out + (size_t)k * (CH * 49) + (size_t)chunk * (512 * 49);
    #pragma unroll
    for (int sub = 0; sub < 2; sub++) {
        if ((tid >> 7) == sub) {
            int cl = tid * 2 - sub * 256;  // 0..254, even
            #pragma unroll
            for (int i = 0; i < 49; i++) {
                sbuf[(cl    ) * 49 + i] = acc[i].x;
                sbuf[(cl + 1) * 49 + i] = acc[i].y;
            }
        }
        __syncthreads();
        const float4* s4 = (const float4*)sbuf;
        float4* o4 = (float4*)(outk + sub * 12544);
        #pragma unroll
        for (int j = 0; j < 13; j++) {     // 13*256 > 3136
            int i = tid + j * 256;
            if (i < 3136) o4[i] = s4[i];
        }
        __syncthreads();
    }
}

// ---------------------------------------------------------------------------
extern "C" void kernel_launch(void* const* d_in, const int* in_sizes, int n_in,
                              void* d_out, int out_size) {
    const float* features = (const float*)d_in[0];
    const float* rois     = (const float*)d_in[1];
    float* out            = (float*)d_out;

    const int smem = 3 * TB_BYTES;         // 96 KB
    static int done = 0;
    if (!done) {
        cudaFuncSetAttribute(roi_pool_kernel,
                             cudaFuncAttributeMaxDynamicSharedMemorySize, smem);
        done = 1;
    }

    dim3 tgrid((NPIX + 127) / 128, CH / 32, BB);   // (20, 32, 4)
    transpose_kernel<<<tgrid, 256>>>(features);
    roi_pool_kernel<<<dim3(KK, 2), 256, smem>>>(rois, out);
}

// round 14
// speedup vs baseline: 1.0684x; 1.0684x over previous
#include <cuda_runtime.h>
#include <cuda_fp16.h>
#include <cstdint>

#define BB 4
#define CH 1024
#define HH 50
#define WW 50
#define KK 512
#define NPIX (HH*WW)              // 2500
#define GPTS 8

// NHWC-transposed features in fp16: [B][H][W][C]  (20.5 MB scratch)
__device__ __align__(16) __half FT[BB * HH * WW * CH];

__device__ __forceinline__ uint32_t smem_u32(const void* p) {
    uint32_t a;
    asm("{ .reg .u64 t; cvta.to.shared.u64 t, %1; cvt.u32.u64 %0, t; }"
        : "=r"(a) : "l"(p));
    return a;
}
#define CP_ASYNC16(s, g) \
    asm volatile("cp.async.ca.shared.global [%0], [%1], 16;" :: "r"(s), "l"(g))
template<int N> __device__ __forceinline__ void cp_wait() {
    asm volatile("cp.async.wait_group %0;" :: "n"(N));
}
__device__ __forceinline__ void cp_commit() {
    asm volatile("cp.async.commit_group;");
}

// ---------------------------------------------------------------------------
// Kernel 1: NCHW fp32 -> NHWC fp16 transpose-convert (measured ~12us)
// ---------------------------------------------------------------------------
__global__ __launch_bounds__(256)
void transpose_kernel(const float* __restrict__ f) {
    __shared__ __align__(16) float tile[32][133];
    const int b  = blockIdx.z;
    const int p0 = blockIdx.x * 128;
    const int c0 = blockIdx.y * 32;
    const int t  = threadIdx.x;

    const float* fb = f + (size_t)b * CH * NPIX + (size_t)c0 * NPIX;
    #pragma unroll
    for (int j = 0; j < 4; j++) {
        int idx = t + j * 256;
        int c = idx >> 5;
        int q = idx & 31;
        int p = p0 + 4 * q;
        float4 v = make_float4(0.f, 0.f, 0.f, 0.f);
        if (p < NPIX) v = *(const float4*)(fb + (size_t)c * NPIX + p);
        tile[c][4 * q + 0] = v.x;
        tile[c][4 * q + 1] = v.y;
        tile[c][4 * q + 2] = v.z;
        tile[c][4 * q + 3] = v.w;
    }
    __syncthreads();

    __half* ob = FT + (size_t)b * NPIX * CH + c0;
    #pragma unroll
    for (int j = 0; j < 2; j++) {
        int idx = t + j * 256;
        int p = idx >> 2;
        int g = idx & 3;
        if (p0 + p < NPIX) {
            __half2 h0 = __floats2half2_rn(tile[8*g + 0][p], tile[8*g + 1][p]);
            __half2 h1 = __floats2half2_rn(tile[8*g + 2][p], tile[8*g + 3][p]);
            __half2 h2 = __floats2half2_rn(tile[8*g + 4][p], tile[8*g + 5][p]);
            __half2 h3 = __floats2half2_rn(tile[8*g + 6][p], tile[8*g + 7][p]);
            uint4 v;
            v.x = *(const unsigned int*)&h0;
            v.y = *(const unsigned int*)&h1;
            v.z = *(const unsigned int*)&h2;
            v.w = *(const unsigned int*)&h3;
            *(uint4*)(ob + (size_t)(p0 + p) * CH + 8 * g) = v;
        }
    }
}

// ---------------------------------------------------------------------------
// Kernel 2: fused RoIAlign + 2x2 avg pool — EXACT R10 frame.
// Grid (K,2): 512 ch/CTA, 256 threads, 2 ch/thread.
// cp.async taps double-buffered, 2 barriers/row, 49xfloat2 acc,
// 4-chunk float4 drain (staging aliases buffer 0).
// ONLY change vs R10: bilinear math in packed fp16 (HMUL2/HFMA2 with
// half2-duplicated weights), single convert of the result to fp32.
// ---------------------------------------------------------------------------
#define TB_BYTES 32768            // one tap buffer: 32 segs x 1KB

extern __shared__ __align__(16) unsigned char dynsmem[];   // 2*TB_BYTES

__global__ __launch_bounds__(256, 2)
void roi_pool_kernel(const float* __restrict__ rois, float* __restrict__ out) {
    const int k     = blockIdx.x;
    const int chunk = blockIdx.y;          // channel half
    const int tid   = threadIdx.x;

    __shared__ __align__(16) __half2 s_wh[GPTS][GPTS][4];  // dup'd fp16 weights
    __shared__ float s_wx[GPTS], s_wy[GPTS], s_vx[GPTS], s_vy[GPTS];
    __shared__ int   s_x0[GPTS], s_y0[GPTS];
    __shared__ int   s_b;

    if (tid < GPTS) {
        float x1 = __ldg(&rois[k * 5 + 1]) * 0.0625f;
        float y1 = __ldg(&rois[k * 5 + 2]) * 0.0625f;
        float x2 = __ldg(&rois[k * 5 + 3]) * 0.0625f;
        float y2 = __ldg(&rois[k * 5 + 4]) * 0.0625f;
        float bh = fmaxf(y2 - y1, 0.0f) * (1.0f / 7.0f);
        float bw = fmaxf(x2 - x1, 0.0f) * (1.0f / 7.0f);
        float xv = x1 + (float)tid * bw;
        float yv = y1 + (float)tid * bh;
        s_vx[tid] = (xv >= 0.0f && xv < (float)WW) ? 1.0f : 0.0f;
        s_vy[tid] = (yv >= 0.0f && yv < (float)HH) ? 1.0f : 0.0f;
        int x0 = (int)floorf(xv);  x0 = min(max(x0, 0), WW - 2);
        int y0 = (int)floorf(yv);  y0 = min(max(y0, 0), HH - 2);
        s_x0[tid] = x0;  s_y0[tid] = y0;
        s_wx[tid] = xv - (float)x0;
        s_wy[tid] = yv - (float)y0;
        if (tid == 0) s_b = (int)__ldg(&rois[k * 5 + 0]);
    }
    __syncthreads();

    if (tid < 64) {
        int gy = tid >> 3, gx = tid & 7;
        float wy = s_wy[gy], wx = s_wx[gx];
        float sc = 0.25f * s_vy[gy] * s_vx[gx];
        s_wh[gy][gx][0] = __float2half2_rn((1.0f - wy) * (1.0f - wx) * sc);
        s_wh[gy][gx][1] = __float2half2_rn((1.0f - wy) * wx * sc);
        s_wh[gy][gx][2] = __float2half2_rn(wy * (1.0f - wx) * sc);
        s_wh[gy][gx][3] = __float2half2_rn(wy * wx * sc);
    }

    // gather role: t4 = tap, col = 16B chunk within 1KB segment
    const int t4  = tid >> 6;
    const int dy  = t4 >> 1, dx = t4 & 1;
    const int col = tid & 63;
    const __half* bbase = FT + (size_t)s_b * (NPIX * CH) + chunk * 512
                             + (size_t)dx * CH + col * 8;
    int xoff[GPTS];
    #pragma unroll
    for (int gx = 0; gx < GPTS; gx++) xoff[gx] = s_x0[gx] * CH;

    const uint32_t tb0 = smem_u32(dynsmem);
    const uint32_t smy = tb0 + (t4 * 1024 + col * 16);

    #define GATHER(gy, bi)                                                  \
        do {                                                                \
            const __half* rb = bbase + (size_t)(s_y0[gy] + dy) * (WW * CH); \
            uint32_t sb = smy + (bi) * TB_BYTES;                            \
            _Pragma("unroll")                                               \
            for (int j = 0; j < 8; j++)                                     \
                CP_ASYNC16(sb + j * 4096, rb + xoff[j]);                    \
            cp_commit();                                                    \
        } while (0)

    GATHER(0, 0);                          // prologue

    float2 acc[49];
    #pragma unroll
    for (int i = 0; i < 49; i++) { acc[i].x = 0.0f; acc[i].y = 0.0f; }

    #pragma unroll
    for (int gy = 0; gy < GPTS; gy++) {
        if (gy < GPTS - 1) GATHER(gy + 1, (gy + 1) & 1);
        if (gy < GPTS - 1) cp_wait<1>(); else cp_wait<0>();
        __syncthreads();                   // row-gy taps visible

        const unsigned char* buf = dynsmem + (gy & 1) * TB_BYTES;
        #pragma unroll
        for (int gx = 0; gx < GPTS; gx++) {
            const uint2 wraw = *(const uint2*)&s_wh[gy][gx][0];
            const __half2 w0 = *(const __half2*)&wraw.x;
            const uint2 wraw2 = *(const uint2*)&s_wh[gy][gx][2];
            __half2 w1; { unsigned int u = wraw.y;  w1 = *(const __half2*)&u; }
            __half2 w2; { unsigned int u = wraw2.x; w2 = *(const __half2*)&u; }
            __half2 w3; { unsigned int u = wraw2.y; w3 = *(const __half2*)&u; }

            const unsigned char* sp = buf + (gx * 4) * 1024 + tid * 4;
            __half2 v00 = *(const __half2*)(sp);
            __half2 v01 = *(const __half2*)(sp + 1024);
            __half2 v10 = *(const __half2*)(sp + 2048);
            __half2 v11 = *(const __half2*)(sp + 3072);

            // packed fp16 bilinear (1 HMUL2 + 3 HFMA2)
            __half2 cur = __hmul2(v00, w0);
            cur = __hfma2(v01, w1, cur);
            cur = __hfma2(v10, w2, cur);
            cur = __hfma2(v11, w3, cur);
            float2 cf = __half22float2(cur);   // single convert, fp32 accum

            if (gy >= 1 && gx >= 1) { acc[(gy-1)*7 + (gx-1)].x += cf.x; acc[(gy-1)*7 + (gx-1)].y += cf.y; }
            if (gy >= 1 && gx <  7) { acc[(gy-1)*7 +  gx   ].x += cf.x; acc[(gy-1)*7 +  gx   ].y += cf.y; }
            if (gy <  7 && gx >= 1) { acc[ gy   *7 + (gx-1)].x += cf.x; acc[ gy   *7 + (gx-1)].y += cf.y; }
            if (gy <  7 && gx <  7) { acc[ gy   *7 +  gx   ].x += cf.x; acc[ gy   *7 +  gx   ].y += cf.y; }
        }
        __syncthreads();                   // done reading buf before refill
    }
    #undef GATHER

    // ---- staged, coalesced output writes (staging aliases buffer 0) ----
    float* sbuf = (float*)dynsmem;         // 25088 B < TB_BYTES
    float* outk = out + (size_t)k * (CH * 49) + (size_t)chunk * (512 * 49);
    #pragma unroll
    for (int sub = 0; sub < 4; sub++) {
        if ((tid >> 6) == sub) {
            int cl = tid * 2 - sub * 128;
            #pragma unroll
            for (int i = 0; i < 49; i++) {
                sbuf[(cl    ) * 49 + i] = acc[i].x;
                sbuf[(cl + 1) * 49 + i] = acc[i].y;
            }
        }
        __syncthreads();
        const float4* s4 = (const float4*)sbuf;
        float4* o4 = (float4*)(outk + sub * 6272);
        #pragma unroll
        for (int j = 0; j < 7; j++) {
            int i = tid + j * 256;
            if (i < 1568) o4[i] = s4[i];
        }
        __syncthreads();
    }
}

// ---------------------------------------------------------------------------
extern "C" void kernel_launch(void* const* d_in, const int* in_sizes, int n_in,
                              void* d_out, int out_size) {
    const float* features = (const float*)d_in[0];
    const float* rois     = (const float*)d_in[1];
    float* out            = (float*)d_out;

    const int smem = 2 * TB_BYTES;         // 64 KB
    static int done = 0;
    if (!done) {
        cudaFuncSetAttribute(roi_pool_kernel,
                             cudaFuncAttributeMaxDynamicSharedMemorySize, smem);
        done = 1;
    }

    dim3 tgrid((NPIX + 127) / 128, CH / 32, BB);   // (20, 32, 4)
    transpose_kernel<<<tgrid, 256>>>(features);
    roi_pool_kernel<<<dim3(KK, 2), 256, smem>>>(rois, out);
}